// round 5
// baseline (speedup 1.0000x reference)
#include <cuda_runtime.h>

// Chamfer distance loss on (2,8,4096,3) fp32 clouds.
// Shared distance matrix: each of 16 batch 4096x4096 matrices evaluated ONCE;
// every pair updates the row-min (pred side) and col-min (targ side). 268M pairs.
//
// Min combining uses inverted-key atomicMax:  key = ~bits(max(d2,0)).
// d2c >= 0  =>  bits in [0,0x7F7FFFFF]  =>  key in [0x80800000,0xFFFFFFFF].
// key is strictly decreasing in d2c, so max(key) == min(d2).  The identity
// element is 0, so the statically zero-initialized buffer needs NO init pass;
// the reduce kernel zeroes each slot after reading it for the next replay.
//
// Kernel 1 (persistent, 296 blocks = 2/SM): pairwise mins.
//   Thread = 8 queries (regs) x 16 targets (smem tile, LDS.128 interleaved).
//   Packed f32x2: per 2 targets  w = fma(m0,y0,fma(m1,y1,fma(m2,y2,x2+h))).
// Kernel 2: sqrt + mean + buffer reset.

#define NPTS    4096
#define NBATCH  16
#define THREADS 256
#define GRID    296
#define TC      256                     // targets per chunk
#define TCH     16                      // target chunks per batch
#define QSN     32                      // query strips (of 128) per batch
#define NCHUNK  (NBATCH * QSN * TCH)    // 8192
#define NQTOT   (2 * NBATCH * NPTS)     // 131072 min slots
#define BIGF    3.4e38f

#define P2_BLOCKS 64
#define P2_THREADS 256

typedef unsigned long long ull;

__device__ unsigned g_key[NQTOT];       // zero-init; [0:65536)=pred rows, rest=targ cols
__device__ float    g_sum;              // zero-init; reset after use
__device__ unsigned g_done;             // zero-init; reset after use

__device__ __forceinline__ ull dupf(float v) {
    ull r; asm("mov.b64 %0, {%1, %1};" : "=l"(r) : "f"(v)); return r;
}
__device__ __forceinline__ ull pk(float lo, float hi) {
    ull r; asm("mov.b64 %0, {%1, %2};" : "=l"(r) : "f"(lo), "f"(hi)); return r;
}
__device__ __forceinline__ unsigned mkkey(float d2) {
    return ~__float_as_uint(fmaxf(d2, 0.0f));
}

__global__ void __launch_bounds__(THREADS, 2)
cd_main_kernel(const float* __restrict__ pred, const float* __restrict__ targ) {
    __shared__ __align__(16) float4 sA[TC / 2];   // (y0_t0,y0_t1,y1_t0,y1_t1)
    __shared__ __align__(16) float4 sB[TC / 2];   // (y2_t0,y2_t1, h_t0, h_t1)
    __shared__ unsigned scol[TC];

    const int tid = threadIdx.x;
    const int tx  = tid & 15;
    const int ty  = tid >> 4;
    const int bid = blockIdx.x;

    scol[tid] = 0u;                     // identity; published by first sync A

    const int c0 = (int)(((long long)bid       * NCHUNK) / GRID);
    const int c1 = (int)(((long long)(bid + 1) * NCHUNK) / GRID);

    ull  m0[8], m1[8], m2[8], x2d[8];
    float ralo[8], rahi[8], calo[8], cahi[8];
    int cur_strip = -1, cur_qbase = 0;

    for (int cid = c0; cid < c1; cid++) {
        const int b  = cid >> 9;        // 512 chunks per batch (32 qs x 16 tc)
        const int rr = cid & 511;
        const int qs = rr >> 4;
        const int tc = rr & 15;

        // ---- query strip management: flush 8 row mins, load 8 new queries ----
        const int strip = (b << 5) | qs;
        if (strip != cur_strip) {
            if (cur_strip >= 0) {
#pragma unroll
                for (int i = 0; i < 8; i++)
                    atomicMax(&g_key[cur_qbase + (ty << 3) + i],
                              mkkey(fminf(ralo[i], rahi[i])));
            }
            cur_strip = strip;
            cur_qbase = (b << 12) + (qs << 7);
            // 8 points = 24 floats = 6 x float4 (96B, 16B-aligned)
            const float4* __restrict__ qv =
                (const float4*)(pred + (size_t)(cur_qbase + (ty << 3)) * 3);
            float4 f[6];
#pragma unroll
            for (int i = 0; i < 6; i++) f[i] = qv[i];
            const float* q = (const float*)f;
#pragma unroll
            for (int i = 0; i < 8; i++) {
                const float x0 = q[i * 3 + 0];
                const float x1 = q[i * 3 + 1];
                const float x2 = q[i * 3 + 2];
                m0[i]  = dupf(-2.0f * x0);
                m1[i]  = dupf(-2.0f * x1);
                m2[i]  = dupf(-2.0f * x2);
                x2d[i] = dupf(x0 * x0 + x1 * x1 + x2 * x2);
                ralo[i] = BIGF; rahi[i] = BIGF;
            }
        }

        // ---- fill target tile: 128 threads x 2 targets, interleaved float4 ----
        if (tid < 128) {
            const float* __restrict__ bp =
                targ + (size_t)((b << 12) + (tc << 8) + tid * 2) * 3;
            const float a0 = bp[0], a1 = bp[1], a2 = bp[2];
            const float b0 = bp[3], b1 = bp[4], b2 = bp[5];
            sA[tid] = make_float4(a0, b0, a1, b1);
            sB[tid] = make_float4(a2, b2,
                                  a0 * a0 + a1 * a1 + a2 * a2,
                                  b0 * b0 + b1 * b1 + b2 * b2);
        }
#pragma unroll
        for (int k = 0; k < 8; k++) { calo[k] = BIGF; cahi[k] = BIGF; }
        __syncthreads();    // A: tile + scol(identity) visible

        // ---- main: 8 target-pairs x 8 queries = 128 pairs/thread ----
#pragma unroll
        for (int k = 0; k < 8; k++) {
            const int pw = tx + (k << 4);
            const float4 ua = sA[pw];     // LDS.128
            const float4 ub = sB[pw];     // LDS.128
            const ull y0p = pk(ua.x, ua.y);
            const ull y1p = pk(ua.z, ua.w);
            const ull y2p = pk(ub.x, ub.y);
            const ull hp  = pk(ub.z, ub.w);
#pragma unroll
            for (int q = 0; q < 8; q++) {
                ull s, w;
                asm("add.rn.f32x2 %0, %1, %2;"     : "=l"(s) : "l"(x2d[q]), "l"(hp));
                asm("fma.rn.f32x2 %0, %1, %2, %3;" : "=l"(w) : "l"(m2[q]), "l"(y2p), "l"(s));
                asm("fma.rn.f32x2 %0, %1, %2, %3;" : "=l"(w) : "l"(m1[q]), "l"(y1p), "l"(w));
                asm("fma.rn.f32x2 %0, %1, %2, %3;" : "=l"(w) : "l"(m0[q]), "l"(y0p), "l"(w));
                float wl, wh;
                asm("mov.b64 {%0, %1}, %2;" : "=f"(wl), "=f"(wh) : "l"(w));
                ralo[q] = fminf(ralo[q], wl);
                rahi[q] = fminf(rahi[q], wh);
                calo[k] = fminf(calo[k], wl);
                cahi[k] = fminf(cahi[k], wh);
            }
        }

        // ---- col merge: shfl pre-merge (ty pairs), smem atomics from half lanes ----
#pragma unroll
        for (int k = 0; k < 8; k++) {
            calo[k] = fminf(calo[k], __shfl_xor_sync(0xFFFFFFFFu, calo[k], 16));
            cahi[k] = fminf(cahi[k], __shfl_xor_sync(0xFFFFFFFFu, cahi[k], 16));
        }
        if ((tid & 16) == 0) {
#pragma unroll
            for (int k = 0; k < 8; k++) {
                const int w2 = (tx << 1) + (k << 5);
                atomicMax(&scol[w2],     mkkey(calo[k]));
                atomicMax(&scol[w2 + 1], mkkey(cahi[k]));
            }
        }
        __syncthreads();    // B: scol complete

        // ---- one global return-less atomicMax per target; reset own slot ----
        atomicMax(&g_key[(NBATCH * NPTS) + (b << 12) + (tc << 8) + tid], scol[tid]);
        scol[tid] = 0u;
    }

    // final row flush
    if (cur_strip >= 0) {
#pragma unroll
        for (int i = 0; i < 8; i++)
            atomicMax(&g_key[cur_qbase + (ty << 3) + i],
                      mkkey(fminf(ralo[i], rahi[i])));
    }
}

// ---- pass 2: sqrt + mean; resets g_key slots (and g_sum/g_done) for next call ----
__global__ void __launch_bounds__(P2_THREADS)
cd_reduce_kernel(float* __restrict__ out) {
    __shared__ float swsum[P2_THREADS / 32];
    const int tid = threadIdx.x;
    float lsum = 0.0f;
    for (int i = blockIdx.x * P2_THREADS + tid; i < NQTOT; i += P2_BLOCKS * P2_THREADS) {
        lsum += sqrtf(__uint_as_float(~g_key[i]));   // key encodes clamped d2
        g_key[i] = 0u;                               // identity for next call
    }
#pragma unroll
    for (int off = 16; off > 0; off >>= 1)
        lsum += __shfl_down_sync(0xFFFFFFFFu, lsum, off);
    const int lane = tid & 31;
    const int wid  = tid >> 5;
    if (lane == 0) swsum[wid] = lsum;
    __syncthreads();
    if (wid == 0) {
        float v = (lane < P2_THREADS / 32) ? swsum[lane] : 0.0f;
#pragma unroll
        for (int off = (P2_THREADS / 32) / 2; off > 0; off >>= 1)
            v += __shfl_down_sync(0xFFFFFFFFu, v, off);
        if (lane == 0) {
            atomicAdd(&g_sum, v);
            __threadfence();
            const unsigned r = atomicAdd(&g_done, 1u);
            if (r == P2_BLOCKS - 1) {
                out[0] = atomicAdd(&g_sum, 0.0f) * (1.0f / (float)(NBATCH * NPTS));
                g_sum = 0.0f;                        // reset for next call
                g_done = 0u;
            }
        }
    }
}

extern "C" void kernel_launch(void* const* d_in, const int* in_sizes, int n_in,
                              void* d_out, int out_size) {
    const float* pred = (const float*)d_in[0];
    const float* targ = (const float*)d_in[1];
    float* out = (float*)d_out;
    cd_main_kernel<<<GRID, THREADS>>>(pred, targ);
    cd_reduce_kernel<<<P2_BLOCKS, P2_THREADS>>>(out);
}